// round 5
// baseline (speedup 1.0000x reference)
#include <cuda_runtime.h>
#include <cuda_bf16.h>
#include <math.h>

// Problem constants
#define B_   4
#define T_   2048
#define C_   1024
#define H_   16
#define D_   64
#define M_   (B_ * T_)        // 8192
#define C3_  (3 * C_)         // 3072

// ---------------------------------------------------------------------------
// Device scratch (no cudaMalloc allowed)
// ---------------------------------------------------------------------------
__device__ __align__(1024) float g_qkv[M_ * C3_];   // rounded tf32, Q pre-scaled
__device__ __align__(1024) float g_xp[M_ * C_];     // x  rounded+permuted
__device__ __align__(1024) float g_yp[M_ * C_];     // y  rounded+permuted
__device__ __align__(1024) float g_wap[C3_ * C_];   // W_attn^T rounded+permuted
__device__ __align__(1024) float g_wpp[C_ * C_];    // W_proj^T rounded+permuted

// ---------------------------------------------------------------------------
// Helpers
// ---------------------------------------------------------------------------
__device__ __forceinline__ unsigned smem_to_u32(const void* p) {
    unsigned a;
    asm("{ .reg .u64 t; cvta.to.shared.u64 t, %1; cvt.u32.u64 %0, t; }"
        : "=r"(a) : "l"(p));
    return a;
}

#define CP_ASYNC16(dst, src) \
    asm volatile("cp.async.cg.shared.global [%0], [%1], 16;" \
                 :: "r"(dst), "l"(src) : "memory")

__device__ __forceinline__ unsigned f2tf32(float x) {
    unsigned r;
    asm("cvt.rna.tf32.f32 %0, %1;" : "=r"(r) : "f"(x));
    return r;
}
__device__ __forceinline__ float f2tf32f(float x) {
    return __uint_as_float(f2tf32(x));
}

__device__ __forceinline__ void mma_tf32(float* c, const unsigned* a,
                                         const unsigned* b) {
    asm volatile(
        "mma.sync.aligned.m16n8k8.row.col.f32.tf32.tf32.f32 "
        "{%0,%1,%2,%3}, {%4,%5,%6,%7}, {%8,%9}, {%0,%1,%2,%3};"
        : "+f"(c[0]), "+f"(c[1]), "+f"(c[2]), "+f"(c[3])
        : "r"(a[0]), "r"(a[1]), "r"(a[2]), "r"(a[3]),
          "r"(b[0]), "r"(b[1]));
}

// Permuted layout: within each 32-element K block of row r, element kk sits at
//   p = ((kk&3) ^ (r&3))*8 + (kk>>2)
// so thread (g,t) of an mma fragment reads 8 contiguous floats (2x LDS.128).

// ---------------------------------------------------------------------------
// Prep: x [rows][K] fp32 -> rounded tf32, permuted (row-major kept)
// ---------------------------------------------------------------------------
__global__ void __launch_bounds__(256)
xprep_kernel(const float* __restrict__ x, float* __restrict__ xp, int K) {
    int idx = blockIdx.x * 256 + threadIdx.x;     // float4 index
    int perrow = K >> 2;
    int row = idx / perrow;
    int c = idx - row * perrow;                   // float4 within row
    float4 v = reinterpret_cast<const float4*>(x)[idx];
    int key = row & 3;
    float* dst = xp + (size_t)row * K + ((c >> 3) << 5) + (c & 7);
    dst[(0 ^ key) * 8] = f2tf32f(v.x);
    dst[(1 ^ key) * 8] = f2tf32f(v.y);
    dst[(2 ^ key) * 8] = f2tf32f(v.z);
    dst[(3 ^ key) * 8] = f2tf32f(v.w);
}

// ---------------------------------------------------------------------------
// Prep: W [K][N] fp32 -> Wp [N][K] rounded tf32, permuted
// ---------------------------------------------------------------------------
__global__ void __launch_bounds__(256)
wtprep_kernel(const float* __restrict__ W, float* __restrict__ Wp,
              int K, int N) {
    __shared__ float ts[32][33];
    const int tx = threadIdx.x & 31;
    const int ty = threadIdx.x >> 5;   // 0..7
    const int n0 = blockIdx.x * 32;
    const int k0 = blockIdx.y * 32;
#pragma unroll
    for (int i = 0; i < 4; i++)
        ts[ty + i * 8][tx] = W[(size_t)(k0 + ty + i * 8) * N + n0 + tx];
    __syncthreads();
#pragma unroll
    for (int i = 0; i < 4; i++) {
        int n = n0 + ty + i * 8;
        float v = f2tf32f(ts[tx][ty + i * 8]);
        int p = (((tx & 3) ^ (n & 3)) << 3) + (tx >> 2);
        Wp[(size_t)n * K + k0 + p] = v;
    }
}

// ---------------------------------------------------------------------------
// tf32 tensor-core GEMM on pre-rounded permuted operands.
// C[M,N] = A'[M,K] * B'[N,K]^T.  CTA 128x128, BK=32, 4 warps (2x2, 64x64),
// 3-stage cp.async. round_out: round C to tf32; scale cols < C_ by 1/64.
// ---------------------------------------------------------------------------
#define BM 128
#define BN 128
#define BK 32
#define GSTAGES 3
#define G_LDW 36                         // words per 32-float row (padded)
#define HALF_STAGE_W (128 * G_LDW)       // 4608 words (A or B)
#define STAGE_W (2 * HALF_STAGE_W)       // 9216 words
#define GSMEM_BYTES (GSTAGES * STAGE_W * 4)   // 110592 B

__global__ void __launch_bounds__(128, 2)
gemm_tf32_kernel(const float* __restrict__ A, const float* __restrict__ Bm,
                 float* __restrict__ Cm, int M, int N, int K,
                 int round_out) {
    extern __shared__ __align__(16) float sm[];
    const unsigned sbase = smem_to_u32(sm);

    const int tid = threadIdx.x;
    const int wid = tid >> 5;
    const int lane = tid & 31;
    const int g = lane >> 2;
    const int t = lane & 3;
    const int warp_m = wid & 1;
    const int warp_n = wid >> 1;
    const int m0 = blockIdx.y * BM;
    const int n0 = blockIdx.x * BN;
    const int nchunks = K / BK;
    const int sw8 = (t ^ (g & 3)) * 8;   // thread-constant swizzled group

    float acc[4][8][4];
#pragma unroll
    for (int i = 0; i < 4; i++)
#pragma unroll
        for (int j = 0; j < 8; j++)
#pragma unroll
            for (int r = 0; r < 4; r++) acc[i][j][r] = 0.0f;

    // cp.async one BK-chunk (A'+B' rows are linear 128B segments)
    auto issue = [&](int chunk) {
        const unsigned st = sbase + (unsigned)((chunk % GSTAGES) * STAGE_W * 4);
        const int r = tid >> 3;            // 0..15 base row per iter
        const int c16 = tid & 7;           // 16B chunk in row
#pragma unroll
        for (int i = 0; i < 8; i++) {
            int row = r + i * 16;
            const float* src = A + (size_t)(m0 + row) * K + chunk * BK + c16 * 4;
            unsigned dst = st + (unsigned)((row * G_LDW + c16 * 4) * 4);
            CP_ASYNC16(dst, src);
        }
        const unsigned stb = st + (unsigned)(HALF_STAGE_W * 4);
#pragma unroll
        for (int i = 0; i < 8; i++) {
            int row = r + i * 16;
            const float* src = Bm + (size_t)(n0 + row) * K + chunk * BK + c16 * 4;
            unsigned dst = stb + (unsigned)((row * G_LDW + c16 * 4) * 4);
            CP_ASYNC16(dst, src);
        }
        asm volatile("cp.async.commit_group;" ::: "memory");
    };

    issue(0);
    issue(1);

    for (int c = 0; c < nchunks; c++) {
        if (c < nchunks - 1)
            asm volatile("cp.async.wait_group 1;" ::: "memory");
        else
            asm volatile("cp.async.wait_group 0;" ::: "memory");
        __syncthreads();

        if (c + 2 < nchunks) issue(c + 2);

        const float* As = sm + (c % GSTAGES) * STAGE_W
                          + (warp_m * 64 + g) * G_LDW + sw8;
        const float* Bs = sm + (c % GSTAGES) * STAGE_W + HALF_STAGE_W
                          + (warp_n * 64 + g) * G_LDW + sw8;

#pragma unroll
        for (int kh = 0; kh < 2; kh++) {
            float4 vA0[4], vA1[4], vB[8];
#pragma unroll
            for (int mt = 0; mt < 4; mt++) {
                vA0[mt] = *reinterpret_cast<const float4*>(As + mt * (16 * G_LDW) + kh * 4);
                vA1[mt] = *reinterpret_cast<const float4*>(As + mt * (16 * G_LDW) + 8 * G_LDW + kh * 4);
            }
#pragma unroll
            for (int nt = 0; nt < 8; nt++)
                vB[nt] = *reinterpret_cast<const float4*>(Bs + nt * (8 * G_LDW) + kh * 4);

#pragma unroll
            for (int mt = 0; mt < 4; mt++) {
                unsigned a0[4] = {__float_as_uint(vA0[mt].x), __float_as_uint(vA1[mt].x),
                                  __float_as_uint(vA0[mt].y), __float_as_uint(vA1[mt].y)};
                unsigned a1[4] = {__float_as_uint(vA0[mt].z), __float_as_uint(vA1[mt].z),
                                  __float_as_uint(vA0[mt].w), __float_as_uint(vA1[mt].w)};
#pragma unroll
                for (int nt = 0; nt < 8; nt++) {
                    unsigned b0[2] = {__float_as_uint(vB[nt].x), __float_as_uint(vB[nt].y)};
                    unsigned b1[2] = {__float_as_uint(vB[nt].z), __float_as_uint(vB[nt].w)};
                    mma_tf32(acc[mt][nt], a0, b0);
                    mma_tf32(acc[mt][nt], a1, b1);
                }
            }
        }
    }

    // Epilogue
    const float osc = (round_out && n0 < C_) ? (1.0f / (float)D_) : 1.0f;
#pragma unroll
    for (int mt = 0; mt < 4; mt++) {
        int row0 = m0 + warp_m * 64 + mt * 16 + g;
#pragma unroll
        for (int nt = 0; nt < 8; nt++) {
            int col = n0 + warp_n * 64 + nt * 8 + 2 * t;
            float v0 = acc[mt][nt][0] * osc, v1 = acc[mt][nt][1] * osc;
            float v2 = acc[mt][nt][2] * osc, v3 = acc[mt][nt][3] * osc;
            if (round_out) {
                v0 = f2tf32f(v0); v1 = f2tf32f(v1);
                v2 = f2tf32f(v2); v3 = f2tf32f(v3);
            }
            *reinterpret_cast<float2*>(Cm + (size_t)row0 * N + col) =
                make_float2(v0, v1);
            *reinterpret_cast<float2*>(Cm + (size_t)(row0 + 8) * N + col) =
                make_float2(v2, v3);
        }
    }
}

// ---------------------------------------------------------------------------
// Tensor-core flash attention (tf32 mma, fp32 softmax, causal).
// qkv is pre-rounded to tf32; Q pre-scaled by 1/D. Writes y in the
// rounded+permuted proj-A layout (g_yp).
// ---------------------------------------------------------------------------
#define QK_LD 68
#define V_LD  72
#define ATTN_Q_W   (128 * QK_LD)
#define ATTN_K_W   (64 * QK_LD)
#define ATTN_V_W   (64 * V_LD)
#define ATTN_P_W   (4 * 32 * QK_LD)
#define ATTN2_SMEM_BYTES ((ATTN_Q_W + ATTN_K_W + ATTN_V_W + ATTN_P_W) * 4)

__global__ void __launch_bounds__(128, 2)
attn_tc_kernel(const float* __restrict__ qkv, float* __restrict__ yp) {
    extern __shared__ __align__(16) float sm[];
    float* Qs = sm;                        // [128][68]
    float* Ks = Qs + ATTN_Q_W;             // [64][68]
    float* Vs = Ks + ATTN_K_W;             // [64][72]
    float* Ps = Vs + ATTN_V_W;             // [4][32][68]

    const int tid = threadIdx.x;
    const int wid = tid >> 5;
    const int lane = tid & 31;
    const int g = lane >> 2;
    const int t = lane & 3;
    const int qi = (gridDim.x - 1) - blockIdx.x;   // heavy tiles first
    const int h = blockIdx.y;
    const int b = blockIdx.z;
    const int q0 = qi * 128;
    const size_t row_base = (size_t)b * T_;
    const int hcol = h * D_;

    float* Psw = Ps + wid * 32 * QK_LD;

    // ---- Load Q tile (already rounded + scaled) ----
#pragma unroll
    for (int i = 0; i < 16; i++) {
        int idx = i * 128 + tid;
        int r = idx >> 4;
        int c4 = (idx & 15) * 4;
        float4 v = *reinterpret_cast<const float4*>(
            qkv + (row_base + q0 + r) * C3_ + hcol + c4);
        *reinterpret_cast<float4*>(&Qs[r * QK_LD + c4]) = v;
    }

    float mst[2][2], lst[2][2];
#pragma unroll
    for (int mt = 0; mt < 2; mt++) {
        mst[mt][0] = -1e30f; mst[mt][1] = -1e30f;
        lst[mt][0] = 0.0f;   lst[mt][1] = 0.0f;
    }
    float o[2][8][4];
#pragma unroll
    for (int mt = 0; mt < 2; mt++)
#pragma unroll
        for (int nt = 0; nt < 8; nt++)
#pragma unroll
            for (int r = 0; r < 4; r++) o[mt][nt][r] = 0.0f;

    const int nkt = 2 * qi + 2;
    for (int kt = 0; kt < nkt; kt++) {
        const int k0 = kt * 64;
        __syncthreads();

        // ---- Fill K and V tiles (already rounded) ----
#pragma unroll
        for (int i = 0; i < 8; i++) {
            int idx = i * 128 + tid;
            int r = idx >> 4;
            int c4 = (idx & 15) * 4;
            const float* rp = qkv + (row_base + k0 + r) * C3_ + hcol;
            *reinterpret_cast<float4*>(&Ks[r * QK_LD + c4]) =
                *reinterpret_cast<const float4*>(rp + C_ + c4);
            *reinterpret_cast<float4*>(&Vs[r * V_LD + c4]) =
                *reinterpret_cast<const float4*>(rp + 2 * C_ + c4);
        }
        __syncthreads();

        // ---- S = Q K^T ----
        float sf[2][8][4];
#pragma unroll
        for (int mt = 0; mt < 2; mt++)
#pragma unroll
            for (int nt = 0; nt < 8; nt++)
#pragma unroll
                for (int r = 0; r < 4; r++) sf[mt][nt][r] = 0.0f;

#pragma unroll
        for (int ks = 0; ks < 8; ks++) {
            unsigned a[2][4];
#pragma unroll
            for (int mt = 0; mt < 2; mt++) {
                const float* ap = Qs + (wid * 32 + mt * 16 + g) * QK_LD + ks * 8 + t;
                a[mt][0] = __float_as_uint(ap[0]);
                a[mt][1] = __float_as_uint(ap[8 * QK_LD]);
                a[mt][2] = __float_as_uint(ap[4]);
                a[mt][3] = __float_as_uint(ap[8 * QK_LD + 4]);
            }
#pragma unroll
            for (int nt = 0; nt < 8; nt++) {
                unsigned bb[2];
                const float* bp = Ks + (nt * 8 + g) * QK_LD + ks * 8 + t;
                bb[0] = __float_as_uint(bp[0]);
                bb[1] = __float_as_uint(bp[4]);
                mma_tf32(sf[0][nt], a[0], bb);
                mma_tf32(sf[1][nt], a[1], bb);
            }
        }

        // ---- Masked online softmax ----
        const bool need_mask = (kt >= 2 * qi);
#pragma unroll
        for (int mt = 0; mt < 2; mt++) {
            const int qr0 = q0 + wid * 32 + mt * 16 + g;
            const int qr1 = qr0 + 8;
            float rmax0 = -1e30f, rmax1 = -1e30f;
#pragma unroll
            for (int nt = 0; nt < 8; nt++) {
                if (need_mask) {
                    int kc = k0 + nt * 8 + 2 * t;
                    if (kc > qr0)     sf[mt][nt][0] = -1e30f;
                    if (kc + 1 > qr0) sf[mt][nt][1] = -1e30f;
                    if (kc > qr1)     sf[mt][nt][2] = -1e30f;
                    if (kc + 1 > qr1) sf[mt][nt][3] = -1e30f;
                }
                rmax0 = fmaxf(rmax0, fmaxf(sf[mt][nt][0], sf[mt][nt][1]));
                rmax1 = fmaxf(rmax1, fmaxf(sf[mt][nt][2], sf[mt][nt][3]));
            }
            rmax0 = fmaxf(rmax0, __shfl_xor_sync(0xffffffffu, rmax0, 1));
            rmax0 = fmaxf(rmax0, __shfl_xor_sync(0xffffffffu, rmax0, 2));
            rmax1 = fmaxf(rmax1, __shfl_xor_sync(0xffffffffu, rmax1, 1));
            rmax1 = fmaxf(rmax1, __shfl_xor_sync(0xffffffffu, rmax1, 2));

            const float mn0 = fmaxf(mst[mt][0], rmax0);
            const float mn1 = fmaxf(mst[mt][1], rmax1);
            const float corr0 = __expf(mst[mt][0] - mn0);
            const float corr1 = __expf(mst[mt][1] - mn1);
            float sum0 = 0.0f, sum1 = 0.0f;
#pragma unroll
            for (int nt = 0; nt < 8; nt++) {
                float p0 = __expf(sf[mt][nt][0] - mn0);
                float p1 = __expf(sf[mt][nt][1] - mn0);
                float p2 = __expf(sf[mt][nt][2] - mn1);
                float p3 = __expf(sf[mt][nt][3] - mn1);
                sum0 += p0 + p1;
                sum1 += p2 + p3;
                float* pr0 = Psw + (mt * 16 + g) * QK_LD + nt * 8 + 2 * t;
                float* pr1 = Psw + (mt * 16 + g + 8) * QK_LD + nt * 8 + 2 * t;
                *reinterpret_cast<float2*>(pr0) =
                    make_float2(f2tf32f(p0), f2tf32f(p1));
                *reinterpret_cast<float2*>(pr1) =
                    make_float2(f2tf32f(p2), f2tf32f(p3));
            }
            sum0 += __shfl_xor_sync(0xffffffffu, sum0, 1);
            sum0 += __shfl_xor_sync(0xffffffffu, sum0, 2);
            sum1 += __shfl_xor_sync(0xffffffffu, sum1, 1);
            sum1 += __shfl_xor_sync(0xffffffffu, sum1, 2);

            lst[mt][0] = lst[mt][0] * corr0 + sum0;
            lst[mt][1] = lst[mt][1] * corr1 + sum1;
            mst[mt][0] = mn0;
            mst[mt][1] = mn1;
#pragma unroll
            for (int nt = 0; nt < 8; nt++) {
                o[mt][nt][0] *= corr0;
                o[mt][nt][1] *= corr0;
                o[mt][nt][2] *= corr1;
                o[mt][nt][3] *= corr1;
            }
        }
        __syncwarp();

        // ---- O += P V ----
#pragma unroll
        for (int ks = 0; ks < 8; ks++) {
            unsigned a[2][4];
#pragma unroll
            for (int mt = 0; mt < 2; mt++) {
                const float* ap = Psw + (mt * 16 + g) * QK_LD + ks * 8 + t;
                a[mt][0] = __float_as_uint(ap[0]);
                a[mt][1] = __float_as_uint(ap[8 * QK_LD]);
                a[mt][2] = __float_as_uint(ap[4]);
                a[mt][3] = __float_as_uint(ap[8 * QK_LD + 4]);
            }
#pragma unroll
            for (int nt = 0; nt < 8; nt++) {
                unsigned bb[2];
                const float* bp = Vs + (ks * 8 + t) * V_LD + nt * 8 + g;
                bb[0] = __float_as_uint(bp[0]);
                bb[1] = __float_as_uint(bp[4 * V_LD]);
                mma_tf32(o[0][nt], a[0], bb);
                mma_tf32(o[1][nt], a[1], bb);
            }
        }
    }

    // ---- Epilogue: normalize, round, permuted store into yp ----
    const int key = g & 3;
#pragma unroll
    for (int mt = 0; mt < 2; mt++) {
        const float il0 = 1.0f / lst[mt][0];
        const float il1 = 1.0f / lst[mt][1];
        const size_t r0 = row_base + q0 + wid * 32 + mt * 16 + g;
        const size_t r1 = r0 + 8;
#pragma unroll
        for (int nt = 0; nt < 8; nt++) {
            const int col = hcol + nt * 8 + 2 * t;
            const int blk = (col >> 5) << 5;
            const int kk = col & 31;
            const int j = kk >> 2;                 // same for col, col+1
            const int u0 = ((kk & 3) ^ key) * 8;
            const int u1 = (((kk + 1) & 3) ^ key) * 8;
            float* d0 = yp + r0 * C_ + blk + j;
            float* d1 = yp + r1 * C_ + blk + j;
            d0[u0] = f2tf32f(o[mt][nt][0] * il0);
            d0[u1] = f2tf32f(o[mt][nt][1] * il0);
            d1[u0] = f2tf32f(o[mt][nt][2] * il1);
            d1[u1] = f2tf32f(o[mt][nt][3] * il1);
        }
    }
}

// ---------------------------------------------------------------------------
// Launch
// ---------------------------------------------------------------------------
extern "C" void kernel_launch(void* const* d_in, const int* in_sizes, int n_in,
                              void* d_out, int out_size) {
    const float* x      = (const float*)d_in[0];   // [4,2048,1024]
    const float* W_attn = (const float*)d_in[1];   // [1024,3072]
    const float* W_proj = (const float*)d_in[2];   // [1024,1024]
    float* out = (float*)d_out;

    float *qkv, *xp, *yp, *wap, *wpp;
    cudaGetSymbolAddress((void**)&qkv, g_qkv);
    cudaGetSymbolAddress((void**)&xp, g_xp);
    cudaGetSymbolAddress((void**)&yp, g_yp);
    cudaGetSymbolAddress((void**)&wap, g_wap);
    cudaGetSymbolAddress((void**)&wpp, g_wpp);

    cudaFuncSetAttribute(gemm_tf32_kernel,
                         cudaFuncAttributeMaxDynamicSharedMemorySize, GSMEM_BYTES);
    cudaFuncSetAttribute(attn_tc_kernel,
                         cudaFuncAttributeMaxDynamicSharedMemorySize, ATTN2_SMEM_BYTES);

    // 0) prep: round + permute operands
    xprep_kernel<<<(M_ * C_ / 4) / 256, 256>>>(x, xp, C_);
    wtprep_kernel<<<dim3(C3_ / 32, C_ / 32), 256>>>(W_attn, wap, C_, C3_);
    wtprep_kernel<<<dim3(C_ / 32, C_ / 32), 256>>>(W_proj, wpp, C_, C_);

    // 1) qkv = x @ W_attn  (rounded output, Q cols pre-scaled by 1/D)
    gemm_tf32_kernel<<<dim3(C3_ / BN, M_ / BM), 128, GSMEM_BYTES>>>(
        xp, wap, qkv, M_, C3_, C_, 1);

    // 2) causal attention -> yp (rounded + permuted)
    attn_tc_kernel<<<dim3(T_ / 128, H_, B_), 128, ATTN2_SMEM_BYTES>>>(qkv, yp);

    // 3) out = y @ W_proj  (plain fp32 output)
    gemm_tf32_kernel<<<dim3(C_ / BN, M_ / BM), 128, GSMEM_BYTES>>>(
        yp, wpp, out, M_, C_, C_, 0);
}